// round 14
// baseline (speedup 1.0000x reference)
#include <cuda_runtime.h>
#include <cuda_bf16.h>
#include <cstdint>

// ---------------------------------------------------------------------------
// RNNEncDec: persistent recurrence with GROUP-LOCAL barriers (4 independent
// b-slice groups of 25 blocks) + fused init/convW prologue, A-resident
// pipelined HMMA GEMM (R13 proven), fragment layouts, fused logsumexp.
// ---------------------------------------------------------------------------

#define H     300
#define BATCH 256
#define NX    128
#define NY    128
#define V     32000
#define MROWS (127 * 256)      // 32512 = 254 * 128
#define KPA   320              // padded K: 5 chunks of 64; bias baked at col 304
#define NTILE 250
#define NPART 500              // 2 partials per n-tile (wn halves)

// gemm smem: A 81920 + 2x16384 B ring = 114688 -> 2 CTAs/SM
#define SM_BR   81920
#define SMEM_G  114688

// recurrence persistent kernel geometry
#define GRID_R 100
#define JT     12
#define BT     64
#define CH     100
#define SM_W    0
#define SM_B    (2 * JT * H * 4)
#define SM_BUF0 29696
#define SM_BUF1 (SM_BUF0 + CH * BT * 4)
#define SMEM_R  (SM_BUF1 + CH * BT * 4)    // 80896

// ------------------------- device scratch -----------------------------------
__device__ float g_h[2][H * BATCH];
__device__ __align__(16) __nv_bfloat16 g_AF[(size_t)MROWS * KPA];  // frag layout
__device__ __align__(16) __nv_bfloat16 g_WF[(size_t)V * KPA];      // frag layout
__device__ float g_pM[(size_t)MROWS * NPART];
__device__ float g_pS[(size_t)MROWS * NPART];
__device__ float g_bsum[4064];
__device__ unsigned g_barCnt4[128];   // group*32 stride (sector isolation)
__device__ unsigned g_barGen4[128];

// ------------------------- fragment-layout index maps ------------------------
__device__ __forceinline__ size_t af_idx(int m, int k) {
    int mb = m >> 7, rl = m & 127;
    int wm = rl >> 5, r32 = rl & 31;
    int mt = r32 >> 4, rr = r32 & 15;
    int half = rr >> 3, g = rr & 7;
    int kc = k >> 6, kk = k & 63;
    int ki = kk >> 4, kt = kk & 15;
    int khalf = kt >> 3, kp = kt & 7;
    int tig = kp >> 1, kbit = kp & 1;
    int lane = g * 4 + tig;
    int reg = half + khalf * 2;
    size_t byte = (size_t)mb * 81920 +
        (size_t)(((((wm * 2 + mt) * 5 + kc) * 4 + ki) * 512) +
                 lane * 16 + reg * 4 + kbit * 2);
    return byte >> 1;
}

__device__ __forceinline__ size_t wf_idx(int n, int k) {
    int nb = n >> 7, nl = n & 127;
    int wn = nl >> 6, nt = (nl >> 3) & 7, g = nl & 7;
    int kc = k >> 6, kk = k & 63;
    int ki = kk >> 4, kt = kk & 15;
    int khalf = kt >> 3, kp = kt & 7;
    int tig = kp >> 1, kbit = kp & 1;
    int kpair = ki >> 1, kilo = ki & 1;
    int lane = g * 4 + tig;
    size_t byte = (size_t)nb * 81920 +
        (size_t)((((((wn * 8 + nt) * 5 + kc) * 2 + kpair) * 512)) +
                 lane * 16 + kilo * 8 + khalf * 4 + kbit * 2);
    return byte >> 1;
}

// ------------------------- helpers ------------------------------------------
__device__ __forceinline__ void cpa16(void* dst, const void* src) {
    uint32_t d = (uint32_t)__cvta_generic_to_shared(dst);
    asm volatile("cp.async.cg.shared.global [%0], [%1], 16;\n" :: "r"(d), "l"(src));
}
#define CPA_COMMIT() asm volatile("cp.async.commit_group;\n" ::: "memory")
#define CPA_WAIT1()  asm volatile("cp.async.wait_group 1;\n" ::: "memory")
#define CPA_WAIT0()  asm volatile("cp.async.wait_group 0;\n" ::: "memory")

__device__ __forceinline__ void mma16816(float* c, const uint32_t* a,
                                         uint32_t b0, uint32_t b1) {
    asm volatile(
        "mma.sync.aligned.m16n8k16.row.col.f32.bf16.bf16.f32 "
        "{%0,%1,%2,%3}, {%4,%5,%6,%7}, {%8,%9}, {%0,%1,%2,%3};\n"
        : "+f"(c[0]), "+f"(c[1]), "+f"(c[2]), "+f"(c[3])
        : "r"(a[0]), "r"(a[1]), "r"(a[2]), "r"(a[3]), "r"(b0), "r"(b1));
}

__device__ __forceinline__ void lds128(uint32_t* r, uint32_t addr) {
    asm volatile("ld.shared.v4.u32 {%0,%1,%2,%3}, [%4];"
        : "=r"(r[0]), "=r"(r[1]), "=r"(r[2]), "=r"(r[3]) : "r"(addr));
}

// ------------------------- barrier state reset (each replay) ----------------
__global__ void k_rst() {
    int i = threadIdx.x;
    if (i < 128) { g_barCnt4[i] = 0u; g_barGen4[i] = 0u; }
}

// ------------------------- group-local grid barrier (25 blocks) -------------
__device__ __forceinline__ void gridbar_g(int grp, unsigned gen) {
    __threadfence();
    __syncthreads();
    if (threadIdx.x == 0) {
        unsigned* cnt  = &g_barCnt4[grp * 32];
        unsigned* genp = &g_barGen4[grp * 32];
        unsigned t = atomicAdd(cnt, 1u);
        if (t == 24) {
            *cnt = 0;
            __threadfence();
            atomicExch(genp, gen);
        } else {
            unsigned v;
            do {
                asm volatile("ld.global.cg.u32 %0, [%1];" : "=r"(v) : "l"(genp));
                if (v >= gen) break;
                __nanosleep(40);
            } while (true);
        }
        __threadfence();
    }
    __syncthreads();
}

// ------------------------- persistent recurrence (+ fused init/convW) -------
__global__ void __launch_bounds__(256, 1) k_recur(
    const int*   __restrict__ x,
    const int*   __restrict__ y,
    const float* __restrict__ enc_emb,
    const float* __restrict__ encW,
    const float* __restrict__ encb,
    const float* __restrict__ dec_emb,
    const float* __restrict__ decW,
    const float* __restrict__ decb,
    const float* __restrict__ outW,
    const float* __restrict__ outb)
{
    extern __shared__ __align__(16) unsigned char smem[];
    float* sW   = reinterpret_cast<float*>(smem + SM_W);
    float* sb   = reinterpret_cast<float*>(smem + SM_B);
    float* buf0 = reinterpret_cast<float*>(smem + SM_BUF0);
    float* buf1 = reinterpret_cast<float*>(smem + SM_BUF1);

    int tid = threadIdx.x;
    int bx  = blockIdx.x;
    int grp = bx & 3;
    int j0  = (bx >> 2) * JT;
    int b0  = grp * BT;
    int bl  = tid & 63;
    int jg  = tid >> 6;
    int jA  = j0 + jg * 3;

    // ---- load recurrence weights into smem
    for (int i = tid; i < 2 * JT * H; i += 256) {
        int bank = i / (JT * H);
        int r    = i - bank * (JT * H);
        int j    = r / H, k = r - j * H;
        const float* src = bank ? decW : encW;
        sW[i] = src[(size_t)(j0 + j) * H + k];
    }
    if (tid < JT)          sb[tid] = encb[j0 + tid];
    else if (tid < 2 * JT) sb[tid] = decb[j0 + tid - JT];
    __syncthreads();

    // ---- PROLOGUE 1: outW -> fragment layout (distributed, 20 units/block)
    {
        float* swb = buf0;                   // [16][320] scratch (20KB)
        for (int u = bx; u < V / 16; u += GRID_R) {
            int n0 = u * 16;
            for (int i = tid; i < 16 * 300; i += 256) {
                int r = i / 300, c = i - r * 300;
                swb[r * 320 + c] = outW[(size_t)(n0 + r) * H + c];
            }
            for (int i = tid; i < 16 * 20; i += 256) {
                int r = i / 20, c = 300 + (i % 20);
                swb[r * 320 + c] = (c == 304) ? outb[n0 + r] : 0.f;
            }
            __syncthreads();
            for (int i = tid; i < 640; i += 256) {
                int lane = i & 31, t = i >> 5;
                int kpair = t & 1; t >>= 1;
                int kc = t % 5, c2i = t / 5;
                int g = lane >> 2, tig = lane & 3;
                int nl = c2i * 8 + g;
                int nb = n0 >> 7;
                int c2 = ((n0 >> 3) & 15) + c2i;
                __nv_bfloat16 v[8];
                #pragma unroll
                for (int e = 0; e < 8; e++) {
                    int kilo = e >> 2, khalf = (e >> 1) & 1, kbit = e & 1;
                    int k = kc * 64 + (kpair * 2 + kilo) * 16 + khalf * 8 +
                            tig * 2 + kbit;
                    v[e] = __float2bfloat16(swb[nl * 320 + k]);
                }
                size_t byte = (size_t)nb * 81920 +
                    (size_t)(((c2 * 5 + kc) * 2 + kpair) * 512 + lane * 16);
                *reinterpret_cast<uint4*>((char*)g_WF + byte) =
                    *reinterpret_cast<uint4*>(v);
            }
            __syncthreads();
        }
    }

    // ---- PROLOGUE 2: A kc=4 pad region (zeros + bias-one at col 304)
    for (int i = bx * 256 + tid; i < 254 * 8 * 4 * 32; i += GRID_R * 256) {
        int lane = i & 31;
        int t = i >> 5;
        int ki = t & 3; t >>= 2;
        int mu = t & 7; t >>= 3;
        int mb = t;
        uint4 v = make_uint4(0u, 0u, 0u, 0u);
        if (ki == 3 && (lane & 3) == 0) { v.x = 0x3F80u; v.y = 0x3F80u; }
        char* dst = (char*)g_AF + (size_t)mb * 81920 +
                    (size_t)(((mu * 5 + 4) * 4 + ki) * 512 + lane * 16);
        *reinterpret_cast<uint4*>(dst) = v;
    }

    // ---- PROLOGUE 3: zero this block's h0 slice (j0..j0+11, b0..b0+63)
    for (int i = tid; i < JT * BT; i += 256) {
        int k = j0 + i / BT, b = b0 + (i & 63);
        g_h[0][k * BATCH + b] = 0.f;
    }

    gridbar_g(grp, 1u);      // group's h0 (all 300 rows of this b-slice) ready

    // ---- 255 recurrence steps
    for (int s = 0; s < 255; ++s) {
        const float* hin  = g_h[s & 1];
        float*       hout = g_h[(s & 1) ^ 1];
        int dec = (s >= NX);
        int t   = s - NX;
        const int*   idxp = dec ? (y + t * BATCH) : (x + s * BATCH);
        const float* embp = dec ? dec_emb : enc_emb;
        const float* Wb   = sW + dec * (JT * H);
        const float* bb   = sb + dec * JT;

        int e = idxp[b0 + bl];
        const float* erow = embp + (size_t)e * H + jA;
        float e0 = __ldg(erow), e1 = __ldg(erow + 1), e2 = __ldg(erow + 2);

        #pragma unroll 4
        for (int i = tid; i < CH * 16; i += 256) {
            int k = i >> 4, bq = i & 15;
            cpa16(buf0 + k * BT + bq * 4, hin + k * BATCH + b0 + bq * 4);
        }
        CPA_COMMIT();
        #pragma unroll 4
        for (int i = tid; i < CH * 16; i += 256) {
            int k = i >> 4, bq = i & 15;
            cpa16(buf1 + k * BT + bq * 4, hin + (CH + k) * BATCH + b0 + bq * 4);
        }
        CPA_COMMIT();

        float a0 = 0.f, a1 = 0.f, a2 = 0.f;

        CPA_WAIT1();
        __syncthreads();
        #pragma unroll 5
        for (int kk = 0; kk < CH; kk += 4) {
            float h0 = buf0[(kk + 0) * BT + bl];
            float h1 = buf0[(kk + 1) * BT + bl];
            float h2 = buf0[(kk + 2) * BT + bl];
            float h3 = buf0[(kk + 3) * BT + bl];
            float4 w;
            w = *reinterpret_cast<const float4*>(Wb + (jg * 3 + 0) * H + kk);
            a0 = fmaf(h3, w.w, fmaf(h2, w.z, fmaf(h1, w.y, fmaf(h0, w.x, a0))));
            w = *reinterpret_cast<const float4*>(Wb + (jg * 3 + 1) * H + kk);
            a1 = fmaf(h3, w.w, fmaf(h2, w.z, fmaf(h1, w.y, fmaf(h0, w.x, a1))));
            w = *reinterpret_cast<const float4*>(Wb + (jg * 3 + 2) * H + kk);
            a2 = fmaf(h3, w.w, fmaf(h2, w.z, fmaf(h1, w.y, fmaf(h0, w.x, a2))));
        }
        __syncthreads();

        #pragma unroll 4
        for (int i = tid; i < CH * 16; i += 256) {
            int k = i >> 4, bq = i & 15;
            cpa16(buf0 + k * BT + bq * 4, hin + (2 * CH + k) * BATCH + b0 + bq * 4);
        }
        CPA_COMMIT();

        CPA_WAIT1();
        __syncthreads();
        #pragma unroll 5
        for (int kk = 0; kk < CH; kk += 4) {
            float h0 = buf1[(kk + 0) * BT + bl];
            float h1 = buf1[(kk + 1) * BT + bl];
            float h2 = buf1[(kk + 2) * BT + bl];
            float h3 = buf1[(kk + 3) * BT + bl];
            float4 w;
            w = *reinterpret_cast<const float4*>(Wb + (jg * 3 + 0) * H + CH + kk);
            a0 = fmaf(h3, w.w, fmaf(h2, w.z, fmaf(h1, w.y, fmaf(h0, w.x, a0))));
            w = *reinterpret_cast<const float4*>(Wb + (jg * 3 + 1) * H + CH + kk);
            a1 = fmaf(h3, w.w, fmaf(h2, w.z, fmaf(h1, w.y, fmaf(h0, w.x, a1))));
            w = *reinterpret_cast<const float4*>(Wb + (jg * 3 + 2) * H + CH + kk);
            a2 = fmaf(h3, w.w, fmaf(h2, w.z, fmaf(h1, w.y, fmaf(h0, w.x, a2))));
        }

        CPA_WAIT0();
        __syncthreads();
        #pragma unroll 5
        for (int kk = 0; kk < CH; kk += 4) {
            float h0 = buf0[(kk + 0) * BT + bl];
            float h1 = buf0[(kk + 1) * BT + bl];
            float h2 = buf0[(kk + 2) * BT + bl];
            float h3 = buf0[(kk + 3) * BT + bl];
            float4 w;
            w = *reinterpret_cast<const float4*>(Wb + (jg * 3 + 0) * H + 2 * CH + kk);
            a0 = fmaf(h3, w.w, fmaf(h2, w.z, fmaf(h1, w.y, fmaf(h0, w.x, a0))));
            w = *reinterpret_cast<const float4*>(Wb + (jg * 3 + 1) * H + 2 * CH + kk);
            a1 = fmaf(h3, w.w, fmaf(h2, w.z, fmaf(h1, w.y, fmaf(h0, w.x, a1))));
            w = *reinterpret_cast<const float4*>(Wb + (jg * 3 + 2) * H + 2 * CH + kk);
            a2 = fmaf(h3, w.w, fmaf(h2, w.z, fmaf(h1, w.y, fmaf(h0, w.x, a2))));
        }

        float v0 = fmaxf(a0 + e0 + bb[jg * 3 + 0], 0.f);
        float v1 = fmaxf(a1 + e1 + bb[jg * 3 + 1], 0.f);
        float v2 = fmaxf(a2 + e2 + bb[jg * 3 + 2], 0.f);
        int b = b0 + bl;
        hout[(jA + 0) * BATCH + b] = v0;
        hout[(jA + 1) * BATCH + b] = v1;
        hout[(jA + 2) * BATCH + b] = v2;
        if (dec) {
            int m = t * BATCH + b;
            g_AF[af_idx(m, jA + 0)] = __float2bfloat16(v0);
            g_AF[af_idx(m, jA + 1)] = __float2bfloat16(v1);
            g_AF[af_idx(m, jA + 2)] = __float2bfloat16(v2);
        }

        gridbar_g(grp, (unsigned)(s + 2));
    }
}

// ------------------------- A-resident GEMM + fused partial logsumexp --------
// grid (50, 254): CTA = (5 n-tiles, one 128-row A block). A staged once
// (80KB smem-resident), B 2-slot ring. 8 warps: 4 M(32) x 2 N(64).
__global__ void __launch_bounds__(256, 2) k_gemm() {
    extern __shared__ __align__(16) unsigned char smem[];

    int tid = threadIdx.x;
    int warp = tid >> 5, lane = tid & 31;
    int wm = warp & 3, wn = warp >> 2;
    int g = lane >> 2, tig = lane & 3;

    int mb  = blockIdx.y;
    int nb0 = blockIdx.x * 5;

    uint32_t sA = (uint32_t)__cvta_generic_to_shared(smem);
    uint32_t sB = sA + SM_BR;

    {
        const char* agl = (const char*)g_AF + (size_t)mb * 81920;
        #pragma unroll
        for (int p = 0; p < 20; p++) {
            int i = tid + p * 256;
            cpa16((char*)smem + i * 16, agl + (size_t)i * 16);
        }
        CPA_COMMIT();
    }

    auto stageB = [&](int c) {
        int nb = nb0 + c / 5, kc = c % 5;
        char* dst = (char*)smem + SM_BR + (c & 1) * 16384;
        const char* src = (const char*)g_WF + (size_t)nb * 81920 +
                          (size_t)kc * 1024;
        #pragma unroll
        for (int p = 0; p < 4; p++) {
            int i = tid + p * 256;
            int c2 = i >> 6, r = i & 63;
            cpa16(dst + c2 * 1024 + r * 16, src + (size_t)c2 * 5120 + r * 16);
        }
        CPA_COMMIT();
    };

    stageB(0);
    stageB(1);

    float acc[2][8][4];
    #pragma unroll
    for (int a = 0; a < 2; a++)
        #pragma unroll
        for (int b = 0; b < 8; b++)
            #pragma unroll
            for (int q = 0; q < 4; q++) acc[a][b][q] = 0.f;

    #pragma unroll 1
    for (int c = 0; c < 25; c++) {
        int kc = c % 5;
        if (c < 24) { CPA_WAIT1(); } else { CPA_WAIT0(); }
        __syncthreads();

        uint32_t slotAddr = sB + (uint32_t)((c & 1) * 16384) + lane * 16;

        uint32_t af[2][4][4];
        #pragma unroll
        for (int mt = 0; mt < 2; mt++) {
            uint32_t abase = sA +
                (uint32_t)((((wm * 2 + mt) * 5 + kc) * 4) * 512) + lane * 16;
            #pragma unroll
            for (int ki = 0; ki < 4; ki++)
                lds128(af[mt][ki], abase + ki * 512);
        }
        #pragma unroll
        for (int nt = 0; nt < 8; nt++) {
            uint32_t bb = slotAddr + (uint32_t)((wn * 8 + nt) * 1024);
            uint32_t bq[8];
            lds128(bq, bb);
            lds128(bq + 4, bb + 512);
            #pragma unroll
            for (int ki = 0; ki < 4; ki++) {
                uint32_t b0 = bq[(ki >> 1) * 4 + (ki & 1) * 2];
                uint32_t b1 = bq[(ki >> 1) * 4 + (ki & 1) * 2 + 1];
                mma16816(acc[0][nt], af[0][ki], b0, b1);
                mma16816(acc[1][nt], af[1][ki], b0, b1);
            }
        }

        if (kc == 4) {
            int nb = nb0 + c / 5;
            #pragma unroll
            for (int r = 0; r < 4; r++) {
                int mt = r >> 1, hi = r & 1;
                float mx = -3.4e38f;
                #pragma unroll
                for (int nt = 0; nt < 8; nt++) {
                    mx = fmaxf(mx, acc[mt][nt][hi * 2]);
                    mx = fmaxf(mx, acc[mt][nt][hi * 2 + 1]);
                }
                mx = fmaxf(mx, __shfl_xor_sync(0xffffffffu, mx, 1));
                mx = fmaxf(mx, __shfl_xor_sync(0xffffffffu, mx, 2));
                float s = 0.f;
                #pragma unroll
                for (int nt = 0; nt < 8; nt++) {
                    s += __expf(acc[mt][nt][hi * 2]     - mx);
                    s += __expf(acc[mt][nt][hi * 2 + 1] - mx);
                }
                s += __shfl_xor_sync(0xffffffffu, s, 1);
                s += __shfl_xor_sync(0xffffffffu, s, 2);
                if (tig == 0) {
                    int rowL = wm * 32 + mt * 16 + hi * 8 + g;
                    size_t grow = (size_t)(mb * 128 + rowL);
                    g_pM[grow * NPART + nb * 2 + wn] = mx;
                    g_pS[grow * NPART + nb * 2 + wn] = s;
                }
                #pragma unroll
                for (int nt = 0; nt < 8; nt++) {
                    acc[mt][nt][hi * 2] = 0.f;
                    acc[mt][nt][hi * 2 + 1] = 0.f;
                }
            }
        }

        __syncthreads();
        if (c + 2 < 25) stageB(c + 2);
    }
}

// ------------------------- per-row lse + target logit -> CE -----------------
__global__ void __launch_bounds__(256) k_reduce(const int* __restrict__ y) {
    int warp = threadIdx.x >> 5, lane = threadIdx.x & 31;
    int row = blockIdx.x * 8 + warp;
    int t = row >> 8, b = row & 255;
    int n = y[(t + 1) * BATCH + b];

    float dot = 0.f;
    for (int k = lane; k < KPA; k += 32)
        dot += __bfloat162float(g_AF[af_idx(row, k)]) *
               __bfloat162float(g_WF[wf_idx(n, k)]);
    #pragma unroll
    for (int o = 16; o; o >>= 1) dot += __shfl_xor_sync(0xffffffffu, dot, o);

    float m = -3.4e38f, s = 0.f;
    for (int i = lane; i < NPART; i += 32) {
        float tm = g_pM[(size_t)row * NPART + i];
        float ts = g_pS[(size_t)row * NPART + i];
        float nm = fmaxf(m, tm);
        s = s * __expf(m - nm) + ts * __expf(tm - nm);
        m = nm;
    }
    #pragma unroll
    for (int o = 16; o; o >>= 1) {
        float om = __shfl_xor_sync(0xffffffffu, m, o);
        float os = __shfl_xor_sync(0xffffffffu, s, o);
        float nm = fmaxf(m, om);
        s = s * __expf(m - nm) + os * __expf(om - nm);
        m = nm;
    }
    float ce = (m + __logf(s)) - dot;

    __shared__ float sm[8];
    if (lane == 0) sm[warp] = ce;
    __syncthreads();
    if (threadIdx.x == 0) {
        float tt = 0.f;
        #pragma unroll
        for (int i = 0; i < 8; i++) tt += sm[i];
        g_bsum[blockIdx.x] = tt;
    }
}

// ------------------------- final deterministic sum --------------------------
__global__ void k_final(float* out) {
    __shared__ double sm[256];
    int tid = threadIdx.x;
    double s = 0.0;
    for (int i = tid; i < 4064; i += 256) s += (double)g_bsum[i];
    sm[tid] = s;
    __syncthreads();
    for (int o = 128; o; o >>= 1) {
        if (tid < o) sm[tid] += sm[tid + o];
        __syncthreads();
    }
    if (tid == 0) out[0] = (float)(sm[0] * (1.0 / 256.0));
}

// ------------------------- launch -------------------------------------------
extern "C" void kernel_launch(void* const* d_in, const int* in_sizes, int n_in,
                              void* d_out, int out_size) {
    const int*   x       = (const int*)  d_in[0];
    const int*   y       = (const int*)  d_in[1];
    const float* enc_emb = (const float*)d_in[2];
    const float* encW    = (const float*)d_in[3];
    const float* encb    = (const float*)d_in[4];
    const float* dec_emb = (const float*)d_in[5];
    const float* decW    = (const float*)d_in[6];
    const float* decb    = (const float*)d_in[7];
    const float* outW    = (const float*)d_in[8];
    const float* outb    = (const float*)d_in[9];
    float* out = (float*)d_out;

    cudaFuncSetAttribute(k_recur, cudaFuncAttributeMaxDynamicSharedMemorySize,
                         SMEM_R);
    cudaFuncSetAttribute(k_gemm, cudaFuncAttributeMaxDynamicSharedMemorySize,
                         SMEM_G);

    k_rst<<<1, 128>>>();
    k_recur<<<GRID_R, 256, SMEM_R>>>(x, y, enc_emb, encW, encb,
                                     dec_emb, decW, decb, outW, outb);
    k_gemm<<<dim3(50, 254), 256, SMEM_G>>>();
    k_reduce<<<4064, 256>>>(y);
    k_final<<<1, 256>>>(out);
}

// round 15
// speedup vs baseline: 1.0538x; 1.0538x over previous
#include <cuda_runtime.h>
#include <cuda_bf16.h>
#include <cstdint>

// ---------------------------------------------------------------------------
// RNNEncDec: persistent recurrence (one-shot h staging + 2-way k-split
// compute, group-local barriers) + A-resident pipelined HMMA GEMM (proven),
// fragment layouts, fused logsumexp.
// ---------------------------------------------------------------------------

#define H     300
#define BATCH 256
#define NX    128
#define NY    128
#define V     32000
#define MROWS (127 * 256)      // 32512 = 254 * 128
#define KPA   320
#define NTILE 250
#define NPART 500

// gemm smem: A 81920 + 2x16384 B ring = 114688 -> 2 CTAs/SM
#define SM_BR   81920
#define SMEM_G  114688

// recurrence persistent kernel geometry
#define GRID_R 100
#define JT     12
#define BT     64
#define SM_W    0                          // 2*12*300 f32 = 28800
#define SM_B    28800                      // 24 f32 (+pad) -> 128
#define SM_RED  28928                      // 2*6*64 f32 = 3072
#define SM_HS   32000                      // 300*64 f32 = 76800
#define SMEM_R  108800

// ------------------------- device scratch -----------------------------------
__device__ float g_h[2][H * BATCH];
__device__ __align__(16) __nv_bfloat16 g_AF[(size_t)MROWS * KPA];
__device__ __align__(16) __nv_bfloat16 g_WF[(size_t)V * KPA];
__device__ float g_pM[(size_t)MROWS * NPART];
__device__ float g_pS[(size_t)MROWS * NPART];
__device__ float g_bsum[4064];
__device__ unsigned g_barCnt4[128];
__device__ unsigned g_barGen4[128];

// ------------------------- fragment-layout index maps ------------------------
__device__ __forceinline__ size_t af_idx(int m, int k) {
    int mb = m >> 7, rl = m & 127;
    int wm = rl >> 5, r32 = rl & 31;
    int mt = r32 >> 4, rr = r32 & 15;
    int half = rr >> 3, g = rr & 7;
    int kc = k >> 6, kk = k & 63;
    int ki = kk >> 4, kt = kk & 15;
    int khalf = kt >> 3, kp = kt & 7;
    int tig = kp >> 1, kbit = kp & 1;
    int lane = g * 4 + tig;
    int reg = half + khalf * 2;
    size_t byte = (size_t)mb * 81920 +
        (size_t)(((((wm * 2 + mt) * 5 + kc) * 4 + ki) * 512) +
                 lane * 16 + reg * 4 + kbit * 2);
    return byte >> 1;
}

__device__ __forceinline__ size_t wf_idx(int n, int k) {
    int nb = n >> 7, nl = n & 127;
    int wn = nl >> 6, nt = (nl >> 3) & 7, g = nl & 7;
    int kc = k >> 6, kk = k & 63;
    int ki = kk >> 4, kt = kk & 15;
    int khalf = kt >> 3, kp = kt & 7;
    int tig = kp >> 1, kbit = kp & 1;
    int kpair = ki >> 1, kilo = ki & 1;
    int lane = g * 4 + tig;
    size_t byte = (size_t)nb * 81920 +
        (size_t)((((((wn * 8 + nt) * 5 + kc) * 2 + kpair) * 512)) +
                 lane * 16 + kilo * 8 + khalf * 4 + kbit * 2);
    return byte >> 1;
}

// ------------------------- helpers ------------------------------------------
__device__ __forceinline__ void cpa16(void* dst, const void* src) {
    uint32_t d = (uint32_t)__cvta_generic_to_shared(dst);
    asm volatile("cp.async.cg.shared.global [%0], [%1], 16;\n" :: "r"(d), "l"(src));
}
#define CPA_COMMIT() asm volatile("cp.async.commit_group;\n" ::: "memory")
#define CPA_WAIT1()  asm volatile("cp.async.wait_group 1;\n" ::: "memory")
#define CPA_WAIT0()  asm volatile("cp.async.wait_group 0;\n" ::: "memory")

__device__ __forceinline__ void mma16816(float* c, const uint32_t* a,
                                         uint32_t b0, uint32_t b1) {
    asm volatile(
        "mma.sync.aligned.m16n8k16.row.col.f32.bf16.bf16.f32 "
        "{%0,%1,%2,%3}, {%4,%5,%6,%7}, {%8,%9}, {%0,%1,%2,%3};\n"
        : "+f"(c[0]), "+f"(c[1]), "+f"(c[2]), "+f"(c[3])
        : "r"(a[0]), "r"(a[1]), "r"(a[2]), "r"(a[3]), "r"(b0), "r"(b1));
}

__device__ __forceinline__ void lds128(uint32_t* r, uint32_t addr) {
    asm volatile("ld.shared.v4.u32 {%0,%1,%2,%3}, [%4];"
        : "=r"(r[0]), "=r"(r[1]), "=r"(r[2]), "=r"(r[3]) : "r"(addr));
}

// ------------------------- barrier state reset (each replay) ----------------
__global__ void k_rst() {
    int i = threadIdx.x;
    if (i < 128) { g_barCnt4[i] = 0u; g_barGen4[i] = 0u; }
}

// ------------------------- group-local grid barrier (25 blocks) -------------
__device__ __forceinline__ void gridbar_g(int grp, unsigned gen) {
    __threadfence();
    __syncthreads();
    if (threadIdx.x == 0) {
        unsigned* cnt  = &g_barCnt4[grp * 32];
        unsigned* genp = &g_barGen4[grp * 32];
        unsigned t = atomicAdd(cnt, 1u);
        if (t == 24) {
            *cnt = 0;
            __threadfence();
            atomicExch(genp, gen);
        } else {
            unsigned v;
            do {
                asm volatile("ld.global.cg.u32 %0, [%1];" : "=r"(v) : "l"(genp));
                if (v >= gen) break;
                __nanosleep(40);
            } while (true);
        }
        __threadfence();
    }
    __syncthreads();
}

// ------------------------- persistent recurrence (+ fused init/convW) -------
__global__ void __launch_bounds__(256, 1) k_recur(
    const int*   __restrict__ x,
    const int*   __restrict__ y,
    const float* __restrict__ enc_emb,
    const float* __restrict__ encW,
    const float* __restrict__ encb,
    const float* __restrict__ dec_emb,
    const float* __restrict__ decW,
    const float* __restrict__ decb,
    const float* __restrict__ outW,
    const float* __restrict__ outb)
{
    extern __shared__ __align__(16) unsigned char smem[];
    float* sW   = reinterpret_cast<float*>(smem + SM_W);
    float* sb   = reinterpret_cast<float*>(smem + SM_B);
    float* sRed = reinterpret_cast<float*>(smem + SM_RED);
    float* hs   = reinterpret_cast<float*>(smem + SM_HS);

    int tid = threadIdx.x;
    int bx  = blockIdx.x;
    int grp = bx & 3;
    int j0  = (bx >> 2) * JT;
    int b0  = grp * BT;
    int bl  = tid & 63;
    int jh  = (tid >> 6) & 1;       // j half: 6 j each
    int kh  = tid >> 7;             // k half: [0,152) / [152,300)
    int jA  = j0 + jh * 6;

    // ---- load recurrence weights into smem
    for (int i = tid; i < 2 * JT * H; i += 256) {
        int bank = i / (JT * H);
        int r    = i - bank * (JT * H);
        int j    = r / H, k = r - j * H;
        const float* src = bank ? decW : encW;
        sW[i] = src[(size_t)(j0 + j) * H + k];
    }
    if (tid < JT)          sb[tid] = encb[j0 + tid];
    else if (tid < 2 * JT) sb[tid] = decb[j0 + tid - JT];
    __syncthreads();

    // ---- PROLOGUE 1: outW -> fragment layout (distributed, uses hs scratch)
    {
        float* swb = hs;                     // [16][320] scratch (20KB)
        for (int u = bx; u < V / 16; u += GRID_R) {
            int n0 = u * 16;
            for (int i = tid; i < 16 * 300; i += 256) {
                int r = i / 300, c = i - r * 300;
                swb[r * 320 + c] = outW[(size_t)(n0 + r) * H + c];
            }
            for (int i = tid; i < 16 * 20; i += 256) {
                int r = i / 20, c = 300 + (i % 20);
                swb[r * 320 + c] = (c == 304) ? outb[n0 + r] : 0.f;
            }
            __syncthreads();
            for (int i = tid; i < 640; i += 256) {
                int lane = i & 31, t = i >> 5;
                int kpair = t & 1; t >>= 1;
                int kc = t % 5, c2i = t / 5;
                int g = lane >> 2, tig = lane & 3;
                int nl = c2i * 8 + g;
                int nb = n0 >> 7;
                int c2 = ((n0 >> 3) & 15) + c2i;
                __nv_bfloat16 v[8];
                #pragma unroll
                for (int e = 0; e < 8; e++) {
                    int kilo = e >> 2, khalf = (e >> 1) & 1, kbit = e & 1;
                    int k = kc * 64 + (kpair * 2 + kilo) * 16 + khalf * 8 +
                            tig * 2 + kbit;
                    v[e] = __float2bfloat16(swb[nl * 320 + k]);
                }
                size_t byte = (size_t)nb * 81920 +
                    (size_t)(((c2 * 5 + kc) * 2 + kpair) * 512 + lane * 16);
                *reinterpret_cast<uint4*>((char*)g_WF + byte) =
                    *reinterpret_cast<uint4*>(v);
            }
            __syncthreads();
        }
    }

    // ---- PROLOGUE 2: A kc=4 pad region (zeros + bias-one at col 304)
    for (int i = bx * 256 + tid; i < 254 * 8 * 4 * 32; i += GRID_R * 256) {
        int lane = i & 31;
        int t = i >> 5;
        int ki = t & 3; t >>= 2;
        int mu = t & 7; t >>= 3;
        int mb = t;
        uint4 v = make_uint4(0u, 0u, 0u, 0u);
        if (ki == 3 && (lane & 3) == 0) { v.x = 0x3F80u; v.y = 0x3F80u; }
        char* dst = (char*)g_AF + (size_t)mb * 81920 +
                    (size_t)(((mu * 5 + 4) * 4 + ki) * 512 + lane * 16);
        *reinterpret_cast<uint4*>(dst) = v;
    }

    // ---- PROLOGUE 3: zero this block's h0 slice
    for (int i = tid; i < JT * BT; i += 256) {
        int k = j0 + i / BT, b = b0 + (i & 63);
        g_h[0][k * BATCH + b] = 0.f;
    }

    gridbar_g(grp, 1u);

    int kbeg = kh ? 152 : 0;
    int kend = kh ? 300 : 152;

    // ---- 255 recurrence steps
    for (int s = 0; s < 255; ++s) {
        const float* hin  = g_h[s & 1];
        float*       hout = g_h[(s & 1) ^ 1];
        int dec = (s >= NX);
        int t   = s - NX;
        const int*   idxp = dec ? (y + t * BATCH) : (x + s * BATCH);
        const float* embp = dec ? dec_emb : enc_emb;
        const float* Wb   = sW + dec * (JT * H);
        const float* bb   = sb + dec * JT;

        // early embedding gather (kh==0 threads only; hides DRAM latency)
        float e0 = 0.f, e1 = 0.f, e2 = 0.f, e3 = 0.f, e4 = 0.f, e5 = 0.f;
        if (kh == 0) {
            int e = idxp[b0 + bl];
            const float* erow = embp + (size_t)e * H + jA;
            e0 = __ldg(erow);     e1 = __ldg(erow + 1);
            e2 = __ldg(erow + 2); e3 = __ldg(erow + 3);
            e4 = __ldg(erow + 4); e5 = __ldg(erow + 5);
        }

        // one-shot staging: all 300 k rows of this b-slice (76.8KB)
        for (int i = tid; i < 300 * 16; i += 256) {
            int k = i >> 4, bq = i & 15;
            cpa16(hs + k * 64 + bq * 4, hin + k * BATCH + b0 + bq * 4);
        }
        CPA_COMMIT();
        CPA_WAIT0();
        __syncthreads();

        float a0 = 0.f, a1 = 0.f, a2 = 0.f, a3 = 0.f, a4 = 0.f, a5 = 0.f;
        const float* Wj = Wb + (jh * 6) * H;

        #pragma unroll 2
        for (int k = kbeg; k < kend; k += 4) {
            float h0 = hs[(k + 0) * 64 + bl];
            float h1 = hs[(k + 1) * 64 + bl];
            float h2 = hs[(k + 2) * 64 + bl];
            float h3 = hs[(k + 3) * 64 + bl];
            float4 w;
            w = *reinterpret_cast<const float4*>(Wj + 0 * H + k);
            a0 = fmaf(h3, w.w, fmaf(h2, w.z, fmaf(h1, w.y, fmaf(h0, w.x, a0))));
            w = *reinterpret_cast<const float4*>(Wj + 1 * H + k);
            a1 = fmaf(h3, w.w, fmaf(h2, w.z, fmaf(h1, w.y, fmaf(h0, w.x, a1))));
            w = *reinterpret_cast<const float4*>(Wj + 2 * H + k);
            a2 = fmaf(h3, w.w, fmaf(h2, w.z, fmaf(h1, w.y, fmaf(h0, w.x, a2))));
            w = *reinterpret_cast<const float4*>(Wj + 3 * H + k);
            a3 = fmaf(h3, w.w, fmaf(h2, w.z, fmaf(h1, w.y, fmaf(h0, w.x, a3))));
            w = *reinterpret_cast<const float4*>(Wj + 4 * H + k);
            a4 = fmaf(h3, w.w, fmaf(h2, w.z, fmaf(h1, w.y, fmaf(h0, w.x, a4))));
            w = *reinterpret_cast<const float4*>(Wj + 5 * H + k);
            a5 = fmaf(h3, w.w, fmaf(h2, w.z, fmaf(h1, w.y, fmaf(h0, w.x, a5))));
        }

        // cross-kh reduce via smem
        if (kh == 1) {
            float* r = sRed + jh * 6 * 64 + bl;
            r[0 * 64] = a0; r[1 * 64] = a1; r[2 * 64] = a2;
            r[3 * 64] = a3; r[4 * 64] = a4; r[5 * 64] = a5;
        }
        __syncthreads();
        if (kh == 0) {
            const float* r = sRed + jh * 6 * 64 + bl;
            a0 += r[0 * 64]; a1 += r[1 * 64]; a2 += r[2 * 64];
            a3 += r[3 * 64]; a4 += r[4 * 64]; a5 += r[5 * 64];

            float v0 = fmaxf(a0 + e0 + bb[jh * 6 + 0], 0.f);
            float v1 = fmaxf(a1 + e1 + bb[jh * 6 + 1], 0.f);
            float v2 = fmaxf(a2 + e2 + bb[jh * 6 + 2], 0.f);
            float v3 = fmaxf(a3 + e3 + bb[jh * 6 + 3], 0.f);
            float v4 = fmaxf(a4 + e4 + bb[jh * 6 + 4], 0.f);
            float v5 = fmaxf(a5 + e5 + bb[jh * 6 + 5], 0.f);
            int b = b0 + bl;
            hout[(jA + 0) * BATCH + b] = v0;
            hout[(jA + 1) * BATCH + b] = v1;
            hout[(jA + 2) * BATCH + b] = v2;
            hout[(jA + 3) * BATCH + b] = v3;
            hout[(jA + 4) * BATCH + b] = v4;
            hout[(jA + 5) * BATCH + b] = v5;
            if (dec) {
                int m = t * BATCH + b;
                g_AF[af_idx(m, jA + 0)] = __float2bfloat16(v0);
                g_AF[af_idx(m, jA + 1)] = __float2bfloat16(v1);
                g_AF[af_idx(m, jA + 2)] = __float2bfloat16(v2);
                g_AF[af_idx(m, jA + 3)] = __float2bfloat16(v3);
                g_AF[af_idx(m, jA + 4)] = __float2bfloat16(v4);
                g_AF[af_idx(m, jA + 5)] = __float2bfloat16(v5);
            }
        }

        gridbar_g(grp, (unsigned)(s + 2));
    }
}

// ------------------------- A-resident GEMM + fused partial logsumexp --------
__global__ void __launch_bounds__(256, 2) k_gemm() {
    extern __shared__ __align__(16) unsigned char smem[];

    int tid = threadIdx.x;
    int warp = tid >> 5, lane = tid & 31;
    int wm = warp & 3, wn = warp >> 2;
    int g = lane >> 2, tig = lane & 3;

    int mb  = blockIdx.y;
    int nb0 = blockIdx.x * 5;

    uint32_t sA = (uint32_t)__cvta_generic_to_shared(smem);
    uint32_t sB = sA + SM_BR;

    {
        const char* agl = (const char*)g_AF + (size_t)mb * 81920;
        #pragma unroll
        for (int p = 0; p < 20; p++) {
            int i = tid + p * 256;
            cpa16((char*)smem + i * 16, agl + (size_t)i * 16);
        }
        CPA_COMMIT();
    }

    auto stageB = [&](int c) {
        int nb = nb0 + c / 5, kc = c % 5;
        char* dst = (char*)smem + SM_BR + (c & 1) * 16384;
        const char* src = (const char*)g_WF + (size_t)nb * 81920 +
                          (size_t)kc * 1024;
        #pragma unroll
        for (int p = 0; p < 4; p++) {
            int i = tid + p * 256;
            int c2 = i >> 6, r = i & 63;
            cpa16(dst + c2 * 1024 + r * 16, src + (size_t)c2 * 5120 + r * 16);
        }
        CPA_COMMIT();
    };

    stageB(0);
    stageB(1);

    float acc[2][8][4];
    #pragma unroll
    for (int a = 0; a < 2; a++)
        #pragma unroll
        for (int b = 0; b < 8; b++)
            #pragma unroll
            for (int q = 0; q < 4; q++) acc[a][b][q] = 0.f;

    #pragma unroll 1
    for (int c = 0; c < 25; c++) {
        int kc = c % 5;
        if (c < 24) { CPA_WAIT1(); } else { CPA_WAIT0(); }
        __syncthreads();

        uint32_t slotAddr = sB + (uint32_t)((c & 1) * 16384) + lane * 16;

        uint32_t af[2][4][4];
        #pragma unroll
        for (int mt = 0; mt < 2; mt++) {
            uint32_t abase = sA +
                (uint32_t)((((wm * 2 + mt) * 5 + kc) * 4) * 512) + lane * 16;
            #pragma unroll
            for (int ki = 0; ki < 4; ki++)
                lds128(af[mt][ki], abase + ki * 512);
        }
        #pragma unroll
        for (int nt = 0; nt < 8; nt++) {
            uint32_t bb = slotAddr + (uint32_t)((wn * 8 + nt) * 1024);
            uint32_t bq[8];
            lds128(bq, bb);
            lds128(bq + 4, bb + 512);
            #pragma unroll
            for (int ki = 0; ki < 4; ki++) {
                uint32_t b0 = bq[(ki >> 1) * 4 + (ki & 1) * 2];
                uint32_t b1 = bq[(ki >> 1) * 4 + (ki & 1) * 2 + 1];
                mma16816(acc[0][nt], af[0][ki], b0, b1);
                mma16816(acc[1][nt], af[1][ki], b0, b1);
            }
        }

        if (kc == 4) {
            int nb = nb0 + c / 5;
            #pragma unroll
            for (int r = 0; r < 4; r++) {
                int mt = r >> 1, hi = r & 1;
                float mx = -3.4e38f;
                #pragma unroll
                for (int nt = 0; nt < 8; nt++) {
                    mx = fmaxf(mx, acc[mt][nt][hi * 2]);
                    mx = fmaxf(mx, acc[mt][nt][hi * 2 + 1]);
                }
                mx = fmaxf(mx, __shfl_xor_sync(0xffffffffu, mx, 1));
                mx = fmaxf(mx, __shfl_xor_sync(0xffffffffu, mx, 2));
                float s = 0.f;
                #pragma unroll
                for (int nt = 0; nt < 8; nt++) {
                    s += __expf(acc[mt][nt][hi * 2]     - mx);
                    s += __expf(acc[mt][nt][hi * 2 + 1] - mx);
                }
                s += __shfl_xor_sync(0xffffffffu, s, 1);
                s += __shfl_xor_sync(0xffffffffu, s, 2);
                if (tig == 0) {
                    int rowL = wm * 32 + mt * 16 + hi * 8 + g;
                    size_t grow = (size_t)(mb * 128 + rowL);
                    g_pM[grow * NPART + nb * 2 + wn] = mx;
                    g_pS[grow * NPART + nb * 2 + wn] = s;
                }
                #pragma unroll
                for (int nt = 0; nt < 8; nt++) {
                    acc[mt][nt][hi * 2] = 0.f;
                    acc[mt][nt][hi * 2 + 1] = 0.f;
                }
            }
        }

        __syncthreads();
        if (c + 2 < 25) stageB(c + 2);
    }
}

// ------------------------- per-row lse + target logit -> CE -----------------
__global__ void __launch_bounds__(256) k_reduce(const int* __restrict__ y) {
    int warp = threadIdx.x >> 5, lane = threadIdx.x & 31;
    int row = blockIdx.x * 8 + warp;
    int t = row >> 8, b = row & 255;
    int n = y[(t + 1) * BATCH + b];

    float dot = 0.f;
    for (int k = lane; k < KPA; k += 32)
        dot += __bfloat162float(g_AF[af_idx(row, k)]) *
               __bfloat162float(g_WF[wf_idx(n, k)]);
    #pragma unroll
    for (int o = 16; o; o >>= 1) dot += __shfl_xor_sync(0xffffffffu, dot, o);

    float m = -3.4e38f, s = 0.f;
    for (int i = lane; i < NPART; i += 32) {
        float tm = g_pM[(size_t)row * NPART + i];
        float ts = g_pS[(size_t)row * NPART + i];
        float nm = fmaxf(m, tm);
        s = s * __expf(m - nm) + ts * __expf(tm - nm);
        m = nm;
    }
    #pragma unroll
    for (int o = 16; o; o >>= 1) {
        float om = __shfl_xor_sync(0xffffffffu, m, o);
        float os = __shfl_xor_sync(0xffffffffu, s, o);
        float nm = fmaxf(m, om);
        s = s * __expf(m - nm) + os * __expf(om - nm);
        m = nm;
    }
    float ce = (m + __logf(s)) - dot;

    __shared__ float sm[8];
    if (lane == 0) sm[warp] = ce;
    __syncthreads();
    if (threadIdx.x == 0) {
        float tt = 0.f;
        #pragma unroll
        for (int i = 0; i < 8; i++) tt += sm[i];
        g_bsum[blockIdx.x] = tt;
    }
}

// ------------------------- final deterministic sum --------------------------
__global__ void k_final(float* out) {
    __shared__ double sm[256];
    int tid = threadIdx.x;
    double s = 0.0;
    for (int i = tid; i < 4064; i += 256) s += (double)g_bsum[i];
    sm[tid] = s;
    __syncthreads();
    for (int o = 128; o; o >>= 1) {
        if (tid < o) sm[tid] += sm[tid + o];
        __syncthreads();
    }
    if (tid == 0) out[0] = (float)(sm[0] * (1.0 / 256.0));
}

// ------------------------- launch -------------------------------------------
extern "C" void kernel_launch(void* const* d_in, const int* in_sizes, int n_in,
                              void* d_out, int out_size) {
    const int*   x       = (const int*)  d_in[0];
    const int*   y       = (const int*)  d_in[1];
    const float* enc_emb = (const float*)d_in[2];
    const float* encW    = (const float*)d_in[3];
    const float* encb    = (const float*)d_in[4];
    const float* dec_emb = (const float*)d_in[5];
    const float* decW    = (const float*)d_in[6];
    const float* decb    = (const float*)d_in[7];
    const float* outW    = (const float*)d_in[8];
    const float* outb    = (const float*)d_in[9];
    float* out = (float*)d_out;

    cudaFuncSetAttribute(k_recur, cudaFuncAttributeMaxDynamicSharedMemorySize,
                         SMEM_R);
    cudaFuncSetAttribute(k_gemm, cudaFuncAttributeMaxDynamicSharedMemorySize,
                         SMEM_G);

    k_rst<<<1, 128>>>();
    k_recur<<<GRID_R, 256, SMEM_R>>>(x, y, enc_emb, encW, encb,
                                     dec_emb, decW, decb, outW, outb);
    k_gemm<<<dim3(50, 254), 256, SMEM_G>>>();
    k_reduce<<<4064, 256>>>(y);
    k_final<<<1, 256>>>(out);
}